// round 14
// baseline (speedup 1.0000x reference)
#include <cuda_runtime.h>
#include <cuda_bf16.h>
#include <cstdint>

#define C_DIM  256      // K
#define HW     4096
#define P_TOT  16384    // M total
#define N_SAMP 2048     // N total
#define NPC    512
#define NCLS   4
#define TMG    64       // M tile per CTA
#define TNB    64       // N tile rows per B chunk
#define KC     128      // K chunk (64x128 bf16 = 16KB per buffer)
#define NCHUNK (N_SAMP / TNB * 2)   // 64 chunk-iters (2 K-chunks per N-tile)

// ---------------- scratch (__device__ globals; no allocs allowed) ----------------
__device__ __align__(16) __nv_bfloat16 g_Xbf[P_TOT * C_DIM];   // [pixel][k]
__device__ __align__(16) __nv_bfloat16 g_Pbf[N_SAMP * C_DIM];  // normalized, [n][k]
__device__ float g_inv10[P_TOT];    // 10 / max(||x||, eps)
__device__ int   g_cls[P_TOT];
__device__ int   g_pcls[N_SAMP];

// ---------------- helpers ----------------
static __device__ __forceinline__ uint32_t smem_u32(const void* p) {
    uint32_t a;
    asm("{ .reg .u64 t; cvta.to.shared.u64 t, %1; cvt.u32.u64 %0, t; }" : "=r"(a) : "l"(p));
    return a;
}
// A staging: [64][256] bf16, row stride 512B, 32 x 16B chunks, XOR-swizzled.
static __device__ __forceinline__ uint32_t swzA(int row, int kc) {
    return (uint32_t)(row * 512 + ((kc ^ (row & 7)) << 4));
}
// B buffer: [64][128] bf16, row stride 256B, 16 x 16B chunks, XOR-swizzled.
static __device__ __forceinline__ uint32_t swzB(int row, int kc) {
    return (uint32_t)(row * 256 + ((kc ^ (row & 7)) << 4));
}
static __device__ __forceinline__ void ldm4(uint32_t* r, uint32_t addr) {
    asm volatile("ldmatrix.sync.aligned.m8n8.x4.shared.b16 {%0,%1,%2,%3}, [%4];"
                 : "=r"(r[0]), "=r"(r[1]), "=r"(r[2]), "=r"(r[3]) : "r"(addr));
}
static __device__ __forceinline__ void mma16816(float* d, const uint32_t* a,
                                                uint32_t b0, uint32_t b1) {
    asm volatile(
        "mma.sync.aligned.m16n8k16.row.col.f32.bf16.bf16.f32 "
        "{%0,%1,%2,%3},{%4,%5,%6,%7},{%8,%9},{%0,%1,%2,%3};"
        : "+f"(d[0]), "+f"(d[1]), "+f"(d[2]), "+f"(d[3])
        : "r"(a[0]), "r"(a[1]), "r"(a[2]), "r"(a[3]), "r"(b0), "r"(b1));
}
static __device__ __forceinline__ void cpasync16(uint32_t dst, const void* src) {
    asm volatile("cp.async.cg.shared.global [%0], [%1], 16;" :: "r"(dst), "l"(src));
}
#define CP_COMMIT() asm volatile("cp.async.commit_group;" ::: "memory")
#define CP_WAIT(n)  asm volatile("cp.async.wait_group %0;" :: "n"(n) : "memory")

// ---------------- kernels ----------------
__global__ void zero_kernel(float* out) { if (threadIdx.x == 0) *out = 0.0f; }

// Normalize past samples -> bf16; per-sample class from one-hot labels.
__global__ void pnorm_kernel(const float* __restrict__ P, const float* __restrict__ L) {
    int n = blockIdx.x;
    int t = threadIdx.x;             // = channel
    float v = P[n * C_DIM + t];
    __shared__ float sh[256];
    sh[t] = v * v;
    __syncthreads();
    for (int s = 128; s > 0; s >>= 1) { if (t < s) sh[t] += sh[t + s]; __syncthreads(); }
    float inv = 1.0f / fmaxf(sqrtf(sh[0]), 1e-8f);
    g_Pbf[n * C_DIM + t] = __float2bfloat16(v * inv);
    if (t == 0) {
        int c = 0; float best = -1.0f;
        #pragma unroll
        for (int k = 0; k < NCLS; k++) { float lv = L[n * NCLS + k]; if (lv > best) { best = lv; c = k; } }
        g_pcls[n] = c;
    }
}

// Transpose X [b][c][v] -> g_Xbf[pixel][c] bf16; norms; pixel class.
__global__ void prep_kernel(const float* __restrict__ X, const float* __restrict__ Y) {
    int p = blockIdx.x * 256 + threadIdx.x;
    int b = p >> 12, v = p & 4095;
    const float* xb = X + (size_t)b * C_DIM * HW + v;
    float nrm = 0.0f;
    for (int c0 = 0; c0 < C_DIM; c0 += 8) {
        uint4 pk;
        __nv_bfloat16* bp = (__nv_bfloat16*)&pk;
        #pragma unroll
        for (int j = 0; j < 8; j++) {
            float x = xb[(size_t)(c0 + j) * HW];
            nrm = fmaf(x, x, nrm);
            bp[j] = __float2bfloat16(x);
        }
        *(uint4*)(&g_Xbf[(size_t)p * C_DIM + c0]) = pk;
    }
    g_inv10[p] = 10.0f / fmaxf(sqrtf(nrm), 1e-8f);
    const float* yb = Y + (size_t)b * NCLS * HW + v;
    int cls = 0; float best = -1.0f;
    #pragma unroll
    for (int k = 0; k < NCLS; k++) { float yv = yb[(size_t)k * HW]; if (yv > best) { best = yv; cls = k; } }
    g_cls[p] = cls;
}

// bf16 mma.sync GEMM: A held in registers, B double-buffered + pipelined.
// One CTA per 64 pixels, full N. 4 warps 2(M)x2(N), warp tile 32x32.
// Static smem 32KB: A staging initially, then B0 @0 (16KB), B1 @16384.
__global__ __launch_bounds__(128) void gemm_kernel(float* __restrict__ out) {
    __shared__ __align__(128) char sm[32768];
    uint32_t sS = smem_u32(sm);
    int t = threadIdx.x, wid = t >> 5, lane = t & 31;
    int mw = wid & 1, nw = wid >> 1;
    int m0 = blockIdx.x * TMG;

    // ---- Stage A (64x256 = 32KB) and hoist this warp's fragments to registers.
    #pragma unroll
    for (int i = 0; i < 16; i++) {
        int idx = t + i * 128;
        int row = idx >> 5, kc = idx & 31;
        cpasync16(sS + swzA(row, kc), g_Xbf + (size_t)(m0 + row) * C_DIM + kc * 8);
    }
    CP_COMMIT();
    CP_WAIT(0);
    __syncthreads();

    uint32_t areg[2][16][4];   // [mi][ks_global][frag] -> 128 regs
    #pragma unroll
    for (int mi = 0; mi < 2; mi++)
        #pragma unroll
        for (int ksg = 0; ksg < 16; ksg++)
            ldm4(areg[mi][ksg], sS + swzA(mw * 32 + mi * 16 + (lane & 15),
                                          ksg * 2 + (lane >> 4)));
    __syncthreads();   // all warps done reading A staging; smem now B buffers

    // Preload B chunk 0 (N-rows 0-63, K 0-127) into buffer 0.
    #pragma unroll
    for (int i = 0; i < 8; i++) {
        int idx = t + i * 128;
        int row = idx >> 4, kc = idx & 15;
        cpasync16(sS + swzB(row, kc), g_Pbf + (size_t)row * C_DIM + kc * 8);
    }
    CP_COMMIT();

    float inv_r[4];
    #pragma unroll
    for (int q = 0; q < 4; q++)
        inv_r[q] = g_inv10[m0 + mw * 32 + (q >> 1) * 16 + (q & 1) * 8 + (lane >> 2)];

    float cls_acc[4][NCLS];
    #pragma unroll
    for (int q = 0; q < 4; q++)
        #pragma unroll
        for (int c = 0; c < NCLS; c++) cls_acc[q][c] = 0.0f;

    float d[2][4][4];   // accumulators, persist across the 2 K-chunks of an N-tile

    for (int it = 0; it < NCHUNK; it++) {
        int kcb = it & 1;          // K-chunk within N-tile
        int nt  = it >> 1;         // N-tile index
        uint32_t sB = sS + (uint32_t)((it & 1) ? 16384 : 0);
        // NOTE: buffer parity == it&1 (chunk 0 -> buf0, alternating)

        // Prefetch chunk it+1 into the other buffer (written by iter it-1's sync).
        if (it + 1 < NCHUNK) {
            int nt1 = (it + 1) >> 1, kcb1 = (it + 1) & 1;
            const __nv_bfloat16* bsrc =
                g_Pbf + (size_t)nt1 * TNB * C_DIM + kcb1 * KC;
            uint32_t dst = sS + (uint32_t)(((it + 1) & 1) ? 16384 : 0);
            #pragma unroll
            for (int i = 0; i < 8; i++) {
                int idx = t + i * 128;
                int row = idx >> 4, kc = idx & 15;
                cpasync16(dst + swzB(row, kc), bsrc + (size_t)row * C_DIM + kc * 8);
            }
            CP_COMMIT();
            CP_WAIT(1);    // chunk it resident; it+1 in flight
        } else {
            CP_WAIT(0);
        }
        __syncthreads();

        if (kcb == 0) {
            #pragma unroll
            for (int mi = 0; mi < 2; mi++)
                #pragma unroll
                for (int nj = 0; nj < 4; nj++)
                    #pragma unroll
                    for (int q = 0; q < 4; q++) d[mi][nj][q] = 0.0f;
        }

        #pragma unroll
        for (int ks = 0; ks < 8; ks++) {
            int ksg = kcb * 8 + ks;
            uint32_t b[2][4];
            #pragma unroll
            for (int bi = 0; bi < 2; bi++)
                ldm4(b[bi], sB + swzB(nw * 32 + bi * 16 + ((lane >> 4) << 3) + (lane & 7),
                                      ks * 2 + ((lane >> 3) & 1)));
            #pragma unroll
            for (int mi = 0; mi < 2; mi++) {
                mma16816(d[mi][0], areg[mi][ksg], b[0][0], b[0][1]);
                mma16816(d[mi][1], areg[mi][ksg], b[0][2], b[0][3]);
                mma16816(d[mi][2], areg[mi][ksg], b[1][0], b[1][1]);
                mma16816(d[mi][3], areg[mi][ksg], b[1][2], b[1][3]);
            }
        }

        if (kcb == 1) {
            // full K accumulated: exp epilogue (all 64 cols share one class)
            int cls = g_pcls[nt * TNB];
            #pragma unroll
            for (int mi = 0; mi < 2; mi++) {
                float s0 = 0.0f, s1 = 0.0f;
                #pragma unroll
                for (int nj = 0; nj < 4; nj++) {
                    s0 += __expf(fmaf(d[mi][nj][0], inv_r[mi * 2], -10.0f))
                        + __expf(fmaf(d[mi][nj][1], inv_r[mi * 2], -10.0f));
                    s1 += __expf(fmaf(d[mi][nj][2], inv_r[mi * 2 + 1], -10.0f))
                        + __expf(fmaf(d[mi][nj][3], inv_r[mi * 2 + 1], -10.0f));
                }
                cls_acc[mi * 2][cls]     += s0;
                cls_acc[mi * 2 + 1][cls] += s1;
            }
        }

        __syncthreads();   // protect this buffer before iter it+1 prefetches into it
    }

    // ---- reduce: quad lanes + the 2 n-warps -> sRed[64][4] ----
    float* sRed = (float*)sm;              // 64 rows x 4 classes = 256 floats
    float* red2 = (float*)(sm + 1024);     // 128 floats block reduce
    sRed[t] = 0.0f; sRed[t + 128] = 0.0f;
    __syncthreads();
    #pragma unroll
    for (int q = 0; q < 4; q++) {
        int row = mw * 32 + (q >> 1) * 16 + (q & 1) * 8 + (lane >> 2);
        #pragma unroll
        for (int c = 0; c < NCLS; c++) {
            float v = cls_acc[q][c];
            v += __shfl_xor_sync(0xFFFFFFFFu, v, 1);
            v += __shfl_xor_sync(0xFFFFFFFFu, v, 2);
            if ((lane & 3) == 0 && v != 0.0f) atomicAdd(&sRed[row * NCLS + c], v);
        }
    }
    __syncthreads();

    float rr = 0.0f;
    if (t < TMG) {
        int p = m0 + t;
        int cl = g_cls[p];
        float v0 = sRed[t * 4], v1 = sRed[t * 4 + 1], v2 = sRed[t * 4 + 2], v3 = sRed[t * 4 + 3];
        float tot = v0 + v1 + v2 + v3;
        float sc = (cl == 0) ? v0 : (cl == 1) ? v1 : (cl == 2) ? v2 : v3;
        rr = (sc + (float)(N_SAMP - NPC)) / ((tot - sc) + (float)NPC);
    }
    red2[t] = rr;
    __syncthreads();
    for (int s = 64; s > 0; s >>= 1) { if (t < s) red2[t] += red2[t + s]; __syncthreads(); }
    if (t == 0) atomicAdd(out, red2[0] * (1.0f / (float)P_TOT));
}

extern "C" void kernel_launch(void* const* d_in, const int* in_sizes, int n_in,
                              void* d_out, int out_size) {
    const float* X = (const float*)d_in[0];   // (4,256,64,64)
    const float* Y = (const float*)d_in[1];   // (4,4,64,64)
    const float* P = (const float*)d_in[2];   // (2048,256)
    const float* L = (const float*)d_in[3];   // (2048,4)
    float* out = (float*)d_out;

    zero_kernel<<<1, 32>>>(out);
    pnorm_kernel<<<N_SAMP, 256>>>(P, L);
    prep_kernel<<<P_TOT / 256, 256>>>(X, Y);
    gemm_kernel<<<P_TOT / TMG, 128>>>(out);
}

// round 15
// speedup vs baseline: 2.0090x; 2.0090x over previous
#include <cuda_runtime.h>
#include <cuda_bf16.h>
#include <cstdint>

#define C_DIM  256      // K
#define HW     4096
#define P_TOT  16384    // M total
#define N_SAMP 2048     // N total
#define NPC    512
#define NCLS   4
#define TMG    64       // M tile per CTA (A tile 64x256 bf16 = 32KB)
#define TNB    64       // N tile per iter (rows of B)
#define KC     128      // K chunk for B (64x128 bf16 = 16KB)
#define NSPLIT 2
#define NHALF  (N_SAMP / NSPLIT)    // 1024
#define NITER  (NHALF / TNB)        // 16

// ---------------- scratch (__device__ globals; no allocs allowed) ----------------
__device__ __align__(16) __nv_bfloat16 g_Xbf[P_TOT * C_DIM];   // [pixel][k]
__device__ __align__(16) __nv_bfloat16 g_Pbf[N_SAMP * C_DIM];  // normalized, [n][k]
__device__ float g_inv10[P_TOT];    // 10 / max(||x||, eps)
__device__ int   g_cls[P_TOT];
__device__ int   g_pcls[N_SAMP];
__device__ float g_s[P_TOT * NCLS]; // per-pixel per-class exp sums

// ---------------- helpers ----------------
static __device__ __forceinline__ uint32_t smem_u32(const void* p) {
    uint32_t a;
    asm("{ .reg .u64 t; cvta.to.shared.u64 t, %1; cvt.u32.u64 %0, t; }" : "=r"(a) : "l"(p));
    return a;
}
// A tile: [64][256] bf16, row stride 512B, 32 x 16B chunks, XOR-swizzled.
static __device__ __forceinline__ uint32_t swzA(int row, int kc) {
    return (uint32_t)(row * 512 + ((kc ^ (row & 7)) << 4));
}
// B tile: [64][128] bf16, row stride 256B, 16 x 16B chunks, XOR-swizzled.
static __device__ __forceinline__ uint32_t swzB(int row, int kc) {
    return (uint32_t)(row * 256 + ((kc ^ (row & 7)) << 4));
}
static __device__ __forceinline__ void ldm4(uint32_t* r, uint32_t addr) {
    asm volatile("ldmatrix.sync.aligned.m8n8.x4.shared.b16 {%0,%1,%2,%3}, [%4];"
                 : "=r"(r[0]), "=r"(r[1]), "=r"(r[2]), "=r"(r[3]) : "r"(addr));
}
static __device__ __forceinline__ void mma16816(float* d, const uint32_t* a,
                                                uint32_t b0, uint32_t b1) {
    asm volatile(
        "mma.sync.aligned.m16n8k16.row.col.f32.bf16.bf16.f32 "
        "{%0,%1,%2,%3},{%4,%5,%6,%7},{%8,%9},{%0,%1,%2,%3};"
        : "+f"(d[0]), "+f"(d[1]), "+f"(d[2]), "+f"(d[3])
        : "r"(a[0]), "r"(a[1]), "r"(a[2]), "r"(a[3]), "r"(b0), "r"(b1));
}
static __device__ __forceinline__ void cpasync16(uint32_t dst, const void* src) {
    asm volatile("cp.async.cg.shared.global [%0], [%1], 16;" :: "r"(dst), "l"(src));
}
#define CP_COMMIT() asm volatile("cp.async.commit_group;" ::: "memory")
#define CP_WAIT0()  asm volatile("cp.async.wait_group 0;" ::: "memory")

// ---------------- kernels ----------------
__global__ void zero_kernel(float* out) {
    int i = blockIdx.x * blockDim.x + threadIdx.x;
    if (i < P_TOT * NCLS) g_s[i] = 0.0f;
    if (i == 0) *out = 0.0f;
}

// Normalize past samples -> bf16; per-sample class from one-hot labels.
__global__ void pnorm_kernel(const float* __restrict__ P, const float* __restrict__ L) {
    int n = blockIdx.x;
    int t = threadIdx.x;             // = channel
    float v = P[n * C_DIM + t];
    __shared__ float sh[256];
    sh[t] = v * v;
    __syncthreads();
    for (int s = 128; s > 0; s >>= 1) { if (t < s) sh[t] += sh[t + s]; __syncthreads(); }
    float inv = 1.0f / fmaxf(sqrtf(sh[0]), 1e-8f);
    g_Pbf[n * C_DIM + t] = __float2bfloat16(v * inv);
    if (t == 0) {
        int c = 0; float best = -1.0f;
        #pragma unroll
        for (int k = 0; k < NCLS; k++) { float lv = L[n * NCLS + k]; if (lv > best) { best = lv; c = k; } }
        g_pcls[n] = c;
    }
}

// Transpose X [b][c][v] -> g_Xbf[pixel][c] bf16; norms; pixel class.
__global__ void prep_kernel(const float* __restrict__ X, const float* __restrict__ Y) {
    int p = blockIdx.x * 256 + threadIdx.x;
    int b = p >> 12, v = p & 4095;
    const float* xb = X + (size_t)b * C_DIM * HW + v;
    float nrm = 0.0f;
    for (int c0 = 0; c0 < C_DIM; c0 += 8) {
        uint4 pk;
        __nv_bfloat16* bp = (__nv_bfloat16*)&pk;
        #pragma unroll
        for (int j = 0; j < 8; j++) {
            float x = xb[(size_t)(c0 + j) * HW];
            nrm = fmaf(x, x, nrm);
            bp[j] = __float2bfloat16(x);
        }
        *(uint4*)(&g_Xbf[(size_t)p * C_DIM + c0]) = pk;
    }
    g_inv10[p] = 10.0f / fmaxf(sqrtf(nrm), 1e-8f);
    const float* yb = Y + (size_t)b * NCLS * HW + v;
    int cls = 0; float best = -1.0f;
    #pragma unroll
    for (int k = 0; k < NCLS; k++) { float yv = yb[(size_t)k * HW]; if (yv > best) { best = yv; cls = k; } }
    g_cls[p] = cls;
}

// bf16 mma.sync GEMM + exp epilogue. CTA = 64 pixels x one N-half (1024 samples).
// 4 warps 2(M)x2(N), warp tile 32x32; B per N-tile in 2 K-chunks of 128.
// Static smem 48KB: A 32KB, B 16KB. (Exact R12 inner structure.)
__global__ __launch_bounds__(128) void gemm_kernel() {
    __shared__ __align__(128) char sm[49152];
    uint32_t sA = smem_u32(sm);
    uint32_t sB = sA + 32768u;
    int t = threadIdx.x, wid = t >> 5, lane = t & 31;
    int mw = wid & 1, nw = wid >> 1;
    int m0 = blockIdx.x * TMG;
    int n0 = blockIdx.y * NHALF;

    // Load A tile: 64 rows x 32 chunks = 2048, 16 per thread.
    #pragma unroll
    for (int i = 0; i < 16; i++) {
        int idx = t + i * 128;
        int row = idx >> 5, kc = idx & 31;
        cpasync16(sA + swzA(row, kc), g_Xbf + (size_t)(m0 + row) * C_DIM + kc * 8);
    }
    CP_COMMIT();

    // rows owned by this lane: m0 + mw*32 + (q>>1)*16 + (q&1)*8 + (lane>>2)
    float inv_r[4];
    #pragma unroll
    for (int q = 0; q < 4; q++)
        inv_r[q] = g_inv10[m0 + mw * 32 + (q >> 1) * 16 + (q & 1) * 8 + (lane >> 2)];

    float cls_acc[4][NCLS];
    #pragma unroll
    for (int q = 0; q < 4; q++)
        #pragma unroll
        for (int c = 0; c < NCLS; c++) cls_acc[q][c] = 0.0f;

    for (int it = 0; it < NITER; it++) {
        float d[2][4][4];   // [mi][nj][quad]
        #pragma unroll
        for (int mi = 0; mi < 2; mi++)
            #pragma unroll
            for (int nj = 0; nj < 4; nj++)
                #pragma unroll
                for (int q = 0; q < 4; q++) d[mi][nj][q] = 0.0f;

        #pragma unroll
        for (int kcb = 0; kcb < 2; kcb++) {
            // Load B chunk: 64 rows x 16 chunks = 1024, 8 per thread.
            const __nv_bfloat16* bsrc =
                g_Pbf + (size_t)(n0 + it * TNB) * C_DIM + kcb * KC;
            #pragma unroll
            for (int i = 0; i < 8; i++) {
                int idx = t + i * 128;
                int row = idx >> 4, kc = idx & 15;
                cpasync16(sB + swzB(row, kc), bsrc + (size_t)row * C_DIM + kc * 8);
            }
            CP_COMMIT();
            CP_WAIT0();
            __syncthreads();

            #pragma unroll
            for (int ks = 0; ks < 8; ks++) {
                uint32_t a[2][4], b[2][4];
                #pragma unroll
                for (int mi = 0; mi < 2; mi++)
                    ldm4(a[mi], sA + swzA(mw * 32 + mi * 16 + (lane & 15),
                                          kcb * 16 + ks * 2 + (lane >> 4)));
                #pragma unroll
                for (int bi = 0; bi < 2; bi++)
                    ldm4(b[bi], sB + swzB(nw * 32 + bi * 16 + ((lane >> 4) << 3) + (lane & 7),
                                          ks * 2 + ((lane >> 3) & 1)));
                #pragma unroll
                for (int mi = 0; mi < 2; mi++) {
                    mma16816(d[mi][0], a[mi], b[0][0], b[0][1]);
                    mma16816(d[mi][1], a[mi], b[0][2], b[0][3]);
                    mma16816(d[mi][2], a[mi], b[1][0], b[1][1]);
                    mma16816(d[mi][3], a[mi], b[1][2], b[1][3]);
                }
            }
            __syncthreads();   // all warps done reading sB before next overwrite
        }

        // epilogue: all 64 cols this iter share one class (512-aligned blocks)
        int cls = g_pcls[n0 + it * TNB];
        #pragma unroll
        for (int mi = 0; mi < 2; mi++) {
            float s0 = 0.0f, s1 = 0.0f;
            #pragma unroll
            for (int nj = 0; nj < 4; nj++) {
                s0 += __expf(fmaf(d[mi][nj][0], inv_r[mi * 2], -10.0f))
                    + __expf(fmaf(d[mi][nj][1], inv_r[mi * 2], -10.0f));
                s1 += __expf(fmaf(d[mi][nj][2], inv_r[mi * 2 + 1], -10.0f))
                    + __expf(fmaf(d[mi][nj][3], inv_r[mi * 2 + 1], -10.0f));
            }
            cls_acc[mi * 2][cls]     += s0;
            cls_acc[mi * 2 + 1][cls] += s1;
        }
    }

    // ---- reduce: quad lanes + the 2 n-warps -> sRed[64][4] -> global atomics ----
    float* sRed = (float*)sm;              // 64 rows x 4 classes = 256 floats
    sRed[t] = 0.0f; sRed[t + 128] = 0.0f;
    __syncthreads();
    #pragma unroll
    for (int q = 0; q < 4; q++) {
        int row = mw * 32 + (q >> 1) * 16 + (q & 1) * 8 + (lane >> 2);
        #pragma unroll
        for (int c = 0; c < NCLS; c++) {
            float v = cls_acc[q][c];
            v += __shfl_xor_sync(0xFFFFFFFFu, v, 1);
            v += __shfl_xor_sync(0xFFFFFFFFu, v, 2);
            if ((lane & 3) == 0 && v != 0.0f) atomicAdd(&sRed[row * NCLS + c], v);
        }
    }
    __syncthreads();
    // two (row, class) entries per thread -> partial sums to global
    if (sRed[t] != 0.0f)
        atomicAdd(&g_s[(size_t)(m0 + (t >> 2)) * NCLS + (t & 3)], sRed[t]);
    if (sRed[t + 128] != 0.0f)
        atomicAdd(&g_s[(size_t)(m0 + 32 + (t >> 2)) * NCLS + (t & 3)], sRed[t + 128]);
}

__global__ void final_kernel(float* out) {
    int p = blockIdx.x * blockDim.x + threadIdx.x;
    float r = 0.0f;
    if (p < P_TOT) {
        int c = g_cls[p];
        float s0 = g_s[p * 4 + 0], s1 = g_s[p * 4 + 1];
        float s2 = g_s[p * 4 + 2], s3 = g_s[p * 4 + 3];
        float tot = s0 + s1 + s2 + s3;
        float sc  = (c == 0) ? s0 : (c == 1) ? s1 : (c == 2) ? s2 : s3;
        r = (sc + (float)(N_SAMP - NPC)) / ((tot - sc) + (float)NPC);
    }
    __shared__ float sh[256];
    sh[threadIdx.x] = r;
    __syncthreads();
    for (int s = 128; s > 0; s >>= 1) {
        if (threadIdx.x < s) sh[threadIdx.x] += sh[threadIdx.x + s];
        __syncthreads();
    }
    if (threadIdx.x == 0) atomicAdd(out, sh[0] * (1.0f / (float)P_TOT));
}

extern "C" void kernel_launch(void* const* d_in, const int* in_sizes, int n_in,
                              void* d_out, int out_size) {
    const float* X = (const float*)d_in[0];   // (4,256,64,64)
    const float* Y = (const float*)d_in[1];   // (4,4,64,64)
    const float* P = (const float*)d_in[2];   // (2048,256)
    const float* L = (const float*)d_in[3];   // (2048,4)
    float* out = (float*)d_out;

    zero_kernel<<<(P_TOT * NCLS + 255) / 256, 256>>>(out);
    pnorm_kernel<<<N_SAMP, 256>>>(P, L);
    prep_kernel<<<P_TOT / 256, 256>>>(X, Y);
    dim3 grid(P_TOT / TMG, NSPLIT);
    gemm_kernel<<<grid, 128>>>();
    final_kernel<<<P_TOT / 256, 256>>>(out);
}